// round 1
// baseline (speedup 1.0000x reference)
#include <cuda_runtime.h>
#include <math.h>

#define NB 4
#define NN 2048
#define DD 128
#define KK 32
#define H1 530      // 2*EIN
#define H1P 544     // padded to 17*32
#define NBI (NB*NN) // 8192

// ---------------- scratch (static device globals; no allocation) ----------------
__device__ float g_A  [NBI * H1];   // feats_i @ W1[0:128]
__device__ float g_Bv [NBI * H1];   // feats_j @ W1[128:256]
__device__ float g_NH [NBI * 256];  // feats   @ node_w1[0:128]
__device__ float g_cm [NBI * 3];    // mean-centered coords
__device__ int   g_nbidx[NBI * KK];
__device__ float g_dk   [NBI * KK];

// ---------------- fast SiLU: FMA-pipe Taylor sigmoid, MUFU fallback -------------
__device__ __forceinline__ float silu_f(float x) {
    float ax = fabsf(x);
    if (ax < 1.0f) {
        // sigmoid(x) = 0.5 + x*(1/4 - x^2/48 + x^4/480 - 17x^6/80640 + 31x^8/1451520)
        float x2 = x * x;
        float s = 31.0f / 1451520.0f;
        s = fmaf(s, x2, -17.0f / 80640.0f);
        s = fmaf(s, x2,  1.0f / 480.0f);
        s = fmaf(s, x2, -1.0f / 48.0f);
        s = fmaf(s, x2,  0.25f);
        return x * fmaf(x, s, 0.5f);
    }
    return x / (1.0f + __expf(-x));
}

// ---------------- mean-center coords ----------------
__global__ void __launch_bounds__(256) k_mean(const float* __restrict__ coors) {
    int b = blockIdx.x, t = threadIdx.x;
    __shared__ float rx[256], ry[256], rz[256];
    const float* cb = coors + (size_t)b * NN * 3;
    float sx = 0.f, sy = 0.f, sz = 0.f;
    for (int j = t; j < NN; j += 256) {
        sx += cb[3 * j]; sy += cb[3 * j + 1]; sz += cb[3 * j + 2];
    }
    rx[t] = sx; ry[t] = sy; rz[t] = sz;
    __syncthreads();
    for (int s = 128; s > 0; s >>= 1) {
        if (t < s) { rx[t] += rx[t + s]; ry[t] += ry[t + s]; rz[t] += rz[t + s]; }
        __syncthreads();
    }
    float mx = rx[0] * (1.0f / NN), my = ry[0] * (1.0f / NN), mz = rz[0] * (1.0f / NN);
    float* cmb = g_cm + (size_t)b * NN * 3;
    for (int j = t; j < NN; j += 256) {
        cmb[3 * j]     = cb[3 * j]     - mx;
        cmb[3 * j + 1] = cb[3 * j + 1] - my;
        cmb[3 * j + 2] = cb[3 * j + 2] - mz;
    }
}

// ---------------- precompute A = F@W1a, Bv = F@W1b (32 nodes / block) -----------
__global__ void __launch_bounds__(256) k_precompAB(const float* __restrict__ feats,
                                                   const float* __restrict__ ew1) {
    int n0 = blockIdx.x * 32;
    __shared__ float sf[32 * 128];
    int t = threadIdx.x;
    for (int idx = t; idx < 32 * 128; idx += 256) sf[idx] = feats[(size_t)n0 * 128 + idx];
    __syncthreads();
    int ng = t >> 5, lane = t & 31;
    const float* f0p = sf + (ng * 4 + 0) * 128;
    const float* f1p = sf + (ng * 4 + 1) * 128;
    const float* f2p = sf + (ng * 4 + 2) * 128;
    const float* f3p = sf + (ng * 4 + 3) * 128;
    for (int cc = 0; cc < H1; cc += 32) {
        int c = cc + lane;
        if (c >= H1) break;
        float a0 = 0.f, a1 = 0.f, a2 = 0.f, a3 = 0.f;
        float b0 = 0.f, b1 = 0.f, b2 = 0.f, b3 = 0.f;
        for (int d = 0; d < 128; d++) {
            float wA = ew1[d * H1 + c];
            float wB = ew1[(128 + d) * H1 + c];
            float f0 = f0p[d], f1 = f1p[d], f2 = f2p[d], f3 = f3p[d];
            a0 = fmaf(f0, wA, a0); a1 = fmaf(f1, wA, a1);
            a2 = fmaf(f2, wA, a2); a3 = fmaf(f3, wA, a3);
            b0 = fmaf(f0, wB, b0); b1 = fmaf(f1, wB, b1);
            b2 = fmaf(f2, wB, b2); b3 = fmaf(f3, wB, b3);
        }
        size_t o = (size_t)(n0 + ng * 4) * H1 + c;
        g_A [o] = a0; g_A [o + H1] = a1; g_A [o + 2 * H1] = a2; g_A [o + 3 * H1] = a3;
        g_Bv[o] = b0; g_Bv[o + H1] = b1; g_Bv[o + 2 * H1] = b2; g_Bv[o + 3 * H1] = b3;
    }
}

// ---------------- precompute NH = F @ node_w1[0:128] ----------------------------
__global__ void __launch_bounds__(256) k_precompNH(const float* __restrict__ feats,
                                                   const float* __restrict__ nw1) {
    int n0 = blockIdx.x * 32;
    __shared__ float sf[32 * 128];
    int t = threadIdx.x;
    for (int idx = t; idx < 32 * 128; idx += 256) sf[idx] = feats[(size_t)n0 * 128 + idx];
    __syncthreads();
    int ng = t >> 5, lane = t & 31;
    const float* f0p = sf + (ng * 4 + 0) * 128;
    const float* f1p = sf + (ng * 4 + 1) * 128;
    const float* f2p = sf + (ng * 4 + 2) * 128;
    const float* f3p = sf + (ng * 4 + 3) * 128;
    for (int cc = 0; cc < 256; cc += 32) {
        int c = cc + lane;
        float a0 = 0.f, a1 = 0.f, a2 = 0.f, a3 = 0.f;
        for (int d = 0; d < 128; d++) {
            float w = nw1[d * 256 + c];
            a0 = fmaf(f0p[d], w, a0); a1 = fmaf(f1p[d], w, a1);
            a2 = fmaf(f2p[d], w, a2); a3 = fmaf(f3p[d], w, a3);
        }
        size_t o = (size_t)(n0 + ng * 4) * 256 + c;
        g_NH[o] = a0; g_NH[o + 256] = a1; g_NH[o + 512] = a2; g_NH[o + 768] = a3;
    }
}

// ---------------- top-K nearest neighbors (block per (b,i)) ---------------------
__global__ void __launch_bounds__(256) k_topk(const float* __restrict__ coors) {
    int bi = blockIdx.x;
    int b = bi >> 11;
    __shared__ float sd[NN];
    __shared__ float wv[8];
    __shared__ int   wi[8];
    int t = threadIdx.x;
    const float FINF = __int_as_float(0x7f800000);
    const float* cb = coors + (size_t)b * NN * 3;
    float cx = coors[(size_t)bi * 3], cy = coors[(size_t)bi * 3 + 1], cz = coors[(size_t)bi * 3 + 2];
    for (int j = t; j < NN; j += 256) {
        float dx = cx - cb[3 * j], dy = cy - cb[3 * j + 1], dz = cz - cb[3 * j + 2];
        sd[j] = dx * dx + dy * dy + dz * dz;
    }
    __syncthreads();
    int lane = t & 31, wid = t >> 5;
    for (int k = 0; k < KK; k++) {
        float bv = FINF; int bj = 0x7fffffff;
        for (int j = t; j < NN; j += 256) {
            float v = sd[j];
            if (v < bv) { bv = v; bj = j; }
        }
        #pragma unroll
        for (int off = 16; off > 0; off >>= 1) {
            float ov = __shfl_xor_sync(0xffffffffu, bv, off);
            int   oi = __shfl_xor_sync(0xffffffffu, bj, off);
            if (ov < bv || (ov == bv && oi < bj)) { bv = ov; bj = oi; }
        }
        if (lane == 0) { wv[wid] = bv; wi[wid] = bj; }
        __syncthreads();
        if (t == 0) {
            float fb = wv[0]; int fi = wi[0];
            #pragma unroll
            for (int w = 1; w < 8; w++)
                if (wv[w] < fb || (wv[w] == fb && wi[w] < fi)) { fb = wv[w]; fi = wi[w]; }
            g_nbidx[(size_t)bi * KK + k] = fi;
            g_dk   [(size_t)bi * KK + k] = fb;
            sd[fi] = FINF;
        }
        __syncthreads();
    }
}

// ---------------- fused edge MLP + coord update + node MLP ----------------------
__global__ void __launch_bounds__(256) k_main(
    const float* __restrict__ feats, const float* __restrict__ coors,
    const float* __restrict__ ew1,  const float* __restrict__ eb1,
    const float* __restrict__ ew2,  const float* __restrict__ eb2,
    const float* __restrict__ cw1g, const float* __restrict__ cb1g,
    const float* __restrict__ cw2g, const float* __restrict__ cb2g,
    const float* __restrict__ xw1g, const float* __restrict__ xb1g,
    const float* __restrict__ xw2g, const float* __restrict__ xb2g,
    const float* __restrict__ nw1,  const float* __restrict__ nb1,
    const float* __restrict__ nw2,  const float* __restrict__ nb2,
    float* __restrict__ out)
{
    extern __shared__ float smx[];
    float* s_base = smx;                     // 544
    float* s_w1c  = s_base + H1P;            // 9*544
    float* s_w2t  = s_w1c + 9 * H1P;         // 16*544 (transposed W2, padded, zero-filled)
    float* s_cw1  = s_w2t + 16 * H1P;        // 1024
    float* s_xw1  = s_cw1 + 1024;            // 1024
    float* s_cb1  = s_xw1 + 1024;            // 64
    float* s_xb1  = s_cb1 + 64;              // 64
    float* s_cw2  = s_xb1 + 64;              // 64
    float* s_xw2  = s_cw2 + 64;              // 64
    float* s_b2   = s_xw2 + 64;              // 16
    float* s_enc  = s_b2 + 16;               // 288
    float* s_macc = s_enc + 9 * KK;          // 16
    float* s_cacc = s_macc + 16;             // 4
    float* s_geo  = s_cacc + 4;              // 8
    float* s_hid  = s_geo + 8;               // 256
    float* s_out0 = s_hid + 256;             // 128
    float* s_out1 = s_out0 + 128;            // 128
    int*   s_nb   = (int*)(s_out1 + 128);    // 32

    int tid = threadIdx.x;
    int bi  = blockIdx.x;
    int b   = bi >> 11;

    for (int c = tid; c < H1P; c += 256)
        s_base[c] = (c < H1) ? (g_A[(size_t)bi * H1 + c] + eb1[c]) : 0.f;
    for (int idx = tid; idx < 9 * H1P; idx += 256) {
        int r = idx / H1P, c = idx - r * H1P;
        s_w1c[idx] = (c < H1) ? ew1[(256 + r) * H1 + c] : 0.f;
    }
    for (int idx = tid; idx < 16 * H1P; idx += 256) {
        int c = idx / H1P, el = idx - c * H1P;
        s_w2t[idx] = (el < H1) ? ew2[el * 16 + c] : 0.f;
    }
    for (int idx = tid; idx < 1024; idx += 256) { s_cw1[idx] = cw1g[idx]; s_xw1[idx] = xw1g[idx]; }
    if (tid < 64) { s_cb1[tid] = cb1g[tid]; s_xb1[tid] = xb1g[tid]; s_cw2[tid] = cw2g[tid]; s_xw2[tid] = xw2g[tid]; }
    if (tid < 16) { s_b2[tid] = eb2[tid]; s_macc[tid] = 0.f; }
    if (tid < 4)  s_cacc[tid] = 0.f;
    if (tid < 32) {
        float d = g_dk[(size_t)bi * KK + tid];
        s_enc[tid * 9 + 0] = sinf(d);
        s_enc[tid * 9 + 1] = sinf(0.5f * d);
        s_enc[tid * 9 + 2] = sinf(0.25f * d);
        s_enc[tid * 9 + 3] = sinf(0.125f * d);
        s_enc[tid * 9 + 4] = cosf(d);
        s_enc[tid * 9 + 5] = cosf(0.5f * d);
        s_enc[tid * 9 + 6] = cosf(0.25f * d);
        s_enc[tid * 9 + 7] = cosf(0.125f * d);
        s_enc[tid * 9 + 8] = d;
        s_nb[tid] = g_nbidx[(size_t)bi * KK + tid];
    }
    if (tid < 3) { s_geo[tid] = coors[(size_t)bi * 3 + tid]; s_geo[3 + tid] = g_cm[(size_t)bi * 3 + tid]; }
    __syncthreads();

    int lane = tid & 31, wid = tid >> 5;
    float cb2r = cb2g[0], xb2r = xb2g[0];
    float ci0 = s_geo[0], ci1 = s_geo[1], ci2 = s_geo[2];
    float ai0 = s_geo[3], ai1 = s_geo[4], ai2 = s_geo[5];
    const float* cb3 = coors + (size_t)b * NN * 3;
    const float* cmb = g_cm  + (size_t)b * NN * 3;
    float caccl = 0.f;

    #pragma unroll 1
    for (int q = 0; q < 4; q++) {
        int e = wid * 4 + q;
        int j = s_nb[e];
        const float* bv = g_Bv + ((size_t)b * NN + j) * H1;
        float e9[9];
        #pragma unroll
        for (int r = 0; r < 9; r++) e9[r] = s_enc[e * 9 + r];

        // h1 = silu(A_i + Bv_j + enc@W1c + b1)  (530 elems, 17 chunks across warp)
        float h[17];
        #pragma unroll
        for (int tt = 0; tt < 17; tt++) {
            int el = tt * 32 + lane;
            float acc = s_base[el];
            if (el < H1) acc += bv[el];
            #pragma unroll
            for (int r = 0; r < 9; r++) acc = fmaf(e9[r], s_w1c[r * H1P + el], acc);
            h[tt] = silu_f(acc);
        }

        // m = silu(h1 @ W2 + b2)  (16 outputs; butterfly -> all lanes hold all m)
        float p[16];
        #pragma unroll
        for (int c = 0; c < 16; c++) {
            const float* w = s_w2t + c * H1P + lane;
            float acc = 0.f;
            #pragma unroll
            for (int tt = 0; tt < 17; tt++) acc = fmaf(h[tt], w[tt * 32], acc);
            p[c] = acc;
        }
        #pragma unroll
        for (int off = 16; off > 0; off >>= 1) {
            #pragma unroll
            for (int c = 0; c < 16; c++) p[c] += __shfl_xor_sync(0xffffffffu, p[c], off);
        }
        float m[16];
        #pragma unroll
        for (int c = 0; c < 16; c++) m[c] = silu_f(p[c] + s_b2[c]);
        if (lane == 0) {
            #pragma unroll
            for (int c = 0; c < 16; c++) atomicAdd(&s_macc[c], m[c]);
        }

        // coor MLPs: 16 -> 64 -> 1 (two of them), warp-parallel over hidden units
        float hA0 = s_cb1[lane], hA1 = s_cb1[lane + 32];
        float hX0 = s_xb1[lane], hX1 = s_xb1[lane + 32];
        #pragma unroll
        for (int c = 0; c < 16; c++) {
            hA0 = fmaf(m[c], s_cw1[c * 64 + lane],      hA0);
            hA1 = fmaf(m[c], s_cw1[c * 64 + lane + 32], hA1);
            hX0 = fmaf(m[c], s_xw1[c * 64 + lane],      hX0);
            hX1 = fmaf(m[c], s_xw1[c * 64 + lane + 32], hX1);
        }
        hA0 = silu_f(hA0); hA1 = silu_f(hA1); hX0 = silu_f(hX0); hX1 = silu_f(hX1);
        float cw = hA0 * s_cw2[lane] + hA1 * s_cw2[lane + 32];
        float xw = hX0 * s_xw2[lane] + hX1 * s_xw2[lane + 32];
        #pragma unroll
        for (int off = 16; off > 0; off >>= 1) {
            cw += __shfl_xor_sync(0xffffffffu, cw, off);
            xw += __shfl_xor_sync(0xffffffffu, xw, off);
        }
        cw += cb2r; xw += xb2r;

        // geometry: rel = c_i - c_j; cross = cm_i x cm_j; lanes 0..2 accumulate comps
        float cj0 = cb3[3 * j], cj1 = cb3[3 * j + 1], cj2 = cb3[3 * j + 2];
        float bj0 = cmb[3 * j], bj1 = cmb[3 * j + 1], bj2 = cmb[3 * j + 2];
        float rr, xx;
        if (lane == 0)      { rr = ci0 - cj0; xx = ai1 * bj2 - ai2 * bj1; }
        else if (lane == 1) { rr = ci1 - cj1; xx = ai2 * bj0 - ai0 * bj2; }
        else                { rr = ci2 - cj2; xx = ai0 * bj1 - ai1 * bj0; }
        if (lane < 3) caccl = fmaf(cw, rr, fmaf(xw, xx, caccl));
    }
    if (lane < 3) atomicAdd(&s_cacc[lane], caccl);
    __syncthreads();

    // node MLP: hidden = silu(NH + m_i @ node_w1[128:144] + b1)
    {
        float hv = g_NH[(size_t)bi * 256 + tid] + nb1[tid];
        #pragma unroll
        for (int c = 0; c < 16; c++) hv = fmaf(s_macc[c], nw1[(128 + c) * 256 + tid], hv);
        s_hid[tid] = silu_f(hv);
    }
    __syncthreads();
    // out = hidden @ node_w2 + b2 + feats (split-K across thread halves)
    {
        int half = tid >> 7, dcol = tid & 127;
        const float* w2 = nw2 + half * 128 * 128 + dcol;
        const float* hh = s_hid + half * 128;
        float acc = 0.f;
        #pragma unroll 8
        for (int qq = 0; qq < 128; qq++) acc = fmaf(hh[qq], w2[qq * 128], acc);
        if (half == 0) s_out0[dcol] = acc; else s_out1[dcol] = acc;
    }
    __syncthreads();
    if (tid < 128) {
        out[(size_t)bi * 128 + tid] =
            s_out0[tid] + s_out1[tid] + nb2[tid] + feats[(size_t)bi * 128 + tid];
    }
    if (tid < 3) {
        float* outc = out + (size_t)NBI * DD;
        outc[(size_t)bi * 3 + tid] = coors[(size_t)bi * 3 + tid] + s_cacc[tid];
    }
}

#define SMEM_BYTES (17324 * 4)

extern "C" void kernel_launch(void* const* d_in, const int* in_sizes, int n_in,
                              void* d_out, int out_size) {
    const float* feats = (const float*)d_in[0];
    const float* coors = (const float*)d_in[1];
    const float* ew1   = (const float*)d_in[2];
    const float* eb1   = (const float*)d_in[3];
    const float* ew2   = (const float*)d_in[4];
    const float* eb2   = (const float*)d_in[5];
    const float* cw1   = (const float*)d_in[6];
    const float* cb1   = (const float*)d_in[7];
    const float* cw2   = (const float*)d_in[8];
    const float* cb2   = (const float*)d_in[9];
    const float* xw1   = (const float*)d_in[10];
    const float* xb1   = (const float*)d_in[11];
    const float* xw2   = (const float*)d_in[12];
    const float* xb2   = (const float*)d_in[13];
    const float* nw1   = (const float*)d_in[14];
    const float* nb1   = (const float*)d_in[15];
    const float* nw2   = (const float*)d_in[16];
    const float* nb2   = (const float*)d_in[17];
    float* out = (float*)d_out;

    cudaFuncSetAttribute(k_main, cudaFuncAttributeMaxDynamicSharedMemorySize, SMEM_BYTES);

    k_mean<<<NB, 256>>>(coors);
    k_precompAB<<<NBI / 32, 256>>>(feats, ew1);
    k_precompNH<<<NBI / 32, 256>>>(feats, nw1);
    k_topk<<<NBI, 256>>>(coors);
    k_main<<<NBI, 256, SMEM_BYTES>>>(feats, coors, ew1, eb1, ew2, eb2,
                                     cw1, cb1, cw2, cb2, xw1, xb1, xw2, xb2,
                                     nw1, nb1, nw2, nb2, out);
}

// round 2
// speedup vs baseline: 1.0004x; 1.0004x over previous
#include <cuda_runtime.h>
#include <math.h>

#define NB 4
#define NN 2048
#define DD 128
#define KK 32
#define H1 530      // 2*EIN
#define H1P 544     // padded to 17*32
#define NBI (NB*NN) // 8192

// ---------------- scratch (static device globals; no allocation) ----------------
__device__ float g_A  [NBI * H1];   // feats_i @ W1[0:128]
__device__ float g_Bv [NBI * H1];   // feats_j @ W1[128:256]
__device__ float g_NH [NBI * 256];  // feats   @ node_w1[0:128]
__device__ float g_cm [NBI * 3];    // mean-centered coords
__device__ int   g_nbidx[NBI * KK];
__device__ float g_dk   [NBI * KK];

// ---------------- fast SiLU: FMA-pipe Taylor sigmoid, MUFU fallback -------------
__device__ __forceinline__ float silu_f(float x) {
    float ax = fabsf(x);
    if (ax < 1.0f) {
        // sigmoid(x) = 0.5 + x*(1/4 - x^2/48 + x^4/480 - 17x^6/80640 + 31x^8/1451520)
        float x2 = x * x;
        float s = 31.0f / 1451520.0f;
        s = fmaf(s, x2, -17.0f / 80640.0f);
        s = fmaf(s, x2,  1.0f / 480.0f);
        s = fmaf(s, x2, -1.0f / 48.0f);
        s = fmaf(s, x2,  0.25f);
        return x * fmaf(x, s, 0.5f);
    }
    return x / (1.0f + __expf(-x));
}

// ---------------- mean-center coords ----------------
__global__ void __launch_bounds__(256) k_mean(const float* __restrict__ coors) {
    int b = blockIdx.x, t = threadIdx.x;
    __shared__ float rx[256], ry[256], rz[256];
    const float* cb = coors + (size_t)b * NN * 3;
    float sx = 0.f, sy = 0.f, sz = 0.f;
    for (int j = t; j < NN; j += 256) {
        sx += cb[3 * j]; sy += cb[3 * j + 1]; sz += cb[3 * j + 2];
    }
    rx[t] = sx; ry[t] = sy; rz[t] = sz;
    __syncthreads();
    for (int s = 128; s > 0; s >>= 1) {
        if (t < s) { rx[t] += rx[t + s]; ry[t] += ry[t + s]; rz[t] += rz[t + s]; }
        __syncthreads();
    }
    float mx = rx[0] * (1.0f / NN), my = ry[0] * (1.0f / NN), mz = rz[0] * (1.0f / NN);
    float* cmb = g_cm + (size_t)b * NN * 3;
    for (int j = t; j < NN; j += 256) {
        cmb[3 * j]     = cb[3 * j]     - mx;
        cmb[3 * j + 1] = cb[3 * j + 1] - my;
        cmb[3 * j + 2] = cb[3 * j + 2] - mz;
    }
}

// ---------------- precompute A = F@W1a, Bv = F@W1b (32 nodes / block) -----------
__global__ void __launch_bounds__(256) k_precompAB(const float* __restrict__ feats,
                                                   const float* __restrict__ ew1) {
    int n0 = blockIdx.x * 32;
    __shared__ float sf[32 * 128];
    int t = threadIdx.x;
    for (int idx = t; idx < 32 * 128; idx += 256) sf[idx] = feats[(size_t)n0 * 128 + idx];
    __syncthreads();
    int ng = t >> 5, lane = t & 31;
    const float* f0p = sf + (ng * 4 + 0) * 128;
    const float* f1p = sf + (ng * 4 + 1) * 128;
    const float* f2p = sf + (ng * 4 + 2) * 128;
    const float* f3p = sf + (ng * 4 + 3) * 128;
    for (int cc = 0; cc < H1; cc += 32) {
        int c = cc + lane;
        if (c >= H1) break;
        float a0 = 0.f, a1 = 0.f, a2 = 0.f, a3 = 0.f;
        float b0 = 0.f, b1 = 0.f, b2 = 0.f, b3 = 0.f;
        for (int d = 0; d < 128; d++) {
            float wA = ew1[d * H1 + c];
            float wB = ew1[(128 + d) * H1 + c];
            float f0 = f0p[d], f1 = f1p[d], f2 = f2p[d], f3 = f3p[d];
            a0 = fmaf(f0, wA, a0); a1 = fmaf(f1, wA, a1);
            a2 = fmaf(f2, wA, a2); a3 = fmaf(f3, wA, a3);
            b0 = fmaf(f0, wB, b0); b1 = fmaf(f1, wB, b1);
            b2 = fmaf(f2, wB, b2); b3 = fmaf(f3, wB, b3);
        }
        size_t o = (size_t)(n0 + ng * 4) * H1 + c;
        g_A [o] = a0; g_A [o + H1] = a1; g_A [o + 2 * H1] = a2; g_A [o + 3 * H1] = a3;
        g_Bv[o] = b0; g_Bv[o + H1] = b1; g_Bv[o + 2 * H1] = b2; g_Bv[o + 3 * H1] = b3;
    }
}

// ---------------- precompute NH = F @ node_w1[0:128] ----------------------------
__global__ void __launch_bounds__(256) k_precompNH(const float* __restrict__ feats,
                                                   const float* __restrict__ nw1) {
    int n0 = blockIdx.x * 32;
    __shared__ float sf[32 * 128];
    int t = threadIdx.x;
    for (int idx = t; idx < 32 * 128; idx += 256) sf[idx] = feats[(size_t)n0 * 128 + idx];
    __syncthreads();
    int ng = t >> 5, lane = t & 31;
    const float* f0p = sf + (ng * 4 + 0) * 128;
    const float* f1p = sf + (ng * 4 + 1) * 128;
    const float* f2p = sf + (ng * 4 + 2) * 128;
    const float* f3p = sf + (ng * 4 + 3) * 128;
    for (int cc = 0; cc < 256; cc += 32) {
        int c = cc + lane;
        float a0 = 0.f, a1 = 0.f, a2 = 0.f, a3 = 0.f;
        for (int d = 0; d < 128; d++) {
            float w = nw1[d * 256 + c];
            a0 = fmaf(f0p[d], w, a0); a1 = fmaf(f1p[d], w, a1);
            a2 = fmaf(f2p[d], w, a2); a3 = fmaf(f3p[d], w, a3);
        }
        size_t o = (size_t)(n0 + ng * 4) * 256 + c;
        g_NH[o] = a0; g_NH[o + 256] = a1; g_NH[o + 512] = a2; g_NH[o + 768] = a3;
    }
}

// ---------------- top-K nearest neighbors (block per (b,i)) ---------------------
__global__ void __launch_bounds__(256) k_topk(const float* __restrict__ coors) {
    int bi = blockIdx.x;
    int b = bi >> 11;
    __shared__ float sd[NN];
    __shared__ float wv[8];
    __shared__ int   wi[8];
    int t = threadIdx.x;
    const float FINF = __int_as_float(0x7f800000);
    const float* cb = coors + (size_t)b * NN * 3;
    float cx = coors[(size_t)bi * 3], cy = coors[(size_t)bi * 3 + 1], cz = coors[(size_t)bi * 3 + 2];
    for (int j = t; j < NN; j += 256) {
        float dx = cx - cb[3 * j], dy = cy - cb[3 * j + 1], dz = cz - cb[3 * j + 2];
        sd[j] = dx * dx + dy * dy + dz * dz;
    }
    __syncthreads();
    int lane = t & 31, wid = t >> 5;
    for (int k = 0; k < KK; k++) {
        float bv = FINF; int bj = 0x7fffffff;
        for (int j = t; j < NN; j += 256) {
            float v = sd[j];
            if (v < bv) { bv = v; bj = j; }
        }
        #pragma unroll
        for (int off = 16; off > 0; off >>= 1) {
            float ov = __shfl_xor_sync(0xffffffffu, bv, off);
            int   oi = __shfl_xor_sync(0xffffffffu, bj, off);
            if (ov < bv || (ov == bv && oi < bj)) { bv = ov; bj = oi; }
        }
        if (lane == 0) { wv[wid] = bv; wi[wid] = bj; }
        __syncthreads();
        if (t == 0) {
            float fb = wv[0]; int fi = wi[0];
            #pragma unroll
            for (int w = 1; w < 8; w++)
                if (wv[w] < fb || (wv[w] == fb && wi[w] < fi)) { fb = wv[w]; fi = wi[w]; }
            g_nbidx[(size_t)bi * KK + k] = fi;
            g_dk   [(size_t)bi * KK + k] = fb;
            sd[fi] = FINF;
        }
        __syncthreads();
    }
}

// ---------------- fused edge MLP + coord update + node MLP ----------------------
__global__ void __launch_bounds__(256) k_main(
    const float* __restrict__ feats, const float* __restrict__ coors,
    const float* __restrict__ ew1,  const float* __restrict__ eb1,
    const float* __restrict__ ew2,  const float* __restrict__ eb2,
    const float* __restrict__ cw1g, const float* __restrict__ cb1g,
    const float* __restrict__ cw2g, const float* __restrict__ cb2g,
    const float* __restrict__ xw1g, const float* __restrict__ xb1g,
    const float* __restrict__ xw2g, const float* __restrict__ xb2g,
    const float* __restrict__ nw1,  const float* __restrict__ nb1,
    const float* __restrict__ nw2,  const float* __restrict__ nb2,
    float* __restrict__ out)
{
    extern __shared__ float smx[];
    float* s_base = smx;                     // 544
    float* s_w1c  = s_base + H1P;            // 9*544
    float* s_w2t  = s_w1c + 9 * H1P;         // 16*544 (transposed W2, padded, zero-filled)
    float* s_cw1  = s_w2t + 16 * H1P;        // 1024
    float* s_xw1  = s_cw1 + 1024;            // 1024
    float* s_cb1  = s_xw1 + 1024;            // 64
    float* s_xb1  = s_cb1 + 64;              // 64
    float* s_cw2  = s_xb1 + 64;              // 64
    float* s_xw2  = s_cw2 + 64;              // 64
    float* s_b2   = s_xw2 + 64;              // 16
    float* s_enc  = s_b2 + 16;               // 288
    float* s_macc = s_enc + 9 * KK;          // 16
    float* s_cacc = s_macc + 16;             // 4
    float* s_geo  = s_cacc + 4;              // 8
    float* s_hid  = s_geo + 8;               // 256
    float* s_out0 = s_hid + 256;             // 128
    float* s_out1 = s_out0 + 128;            // 128
    int*   s_nb   = (int*)(s_out1 + 128);    // 32

    int tid = threadIdx.x;
    int bi  = blockIdx.x;
    int b   = bi >> 11;

    for (int c = tid; c < H1P; c += 256)
        s_base[c] = (c < H1) ? (g_A[(size_t)bi * H1 + c] + eb1[c]) : 0.f;
    for (int idx = tid; idx < 9 * H1P; idx += 256) {
        int r = idx / H1P, c = idx - r * H1P;
        s_w1c[idx] = (c < H1) ? ew1[(256 + r) * H1 + c] : 0.f;
    }
    for (int idx = tid; idx < 16 * H1P; idx += 256) {
        int c = idx / H1P, el = idx - c * H1P;
        s_w2t[idx] = (el < H1) ? ew2[el * 16 + c] : 0.f;
    }
    for (int idx = tid; idx < 1024; idx += 256) { s_cw1[idx] = cw1g[idx]; s_xw1[idx] = xw1g[idx]; }
    if (tid < 64) { s_cb1[tid] = cb1g[tid]; s_xb1[tid] = xb1g[tid]; s_cw2[tid] = cw2g[tid]; s_xw2[tid] = xw2g[tid]; }
    if (tid < 16) { s_b2[tid] = eb2[tid]; s_macc[tid] = 0.f; }
    if (tid < 4)  s_cacc[tid] = 0.f;
    if (tid < 32) {
        float d = g_dk[(size_t)bi * KK + tid];
        s_enc[tid * 9 + 0] = sinf(d);
        s_enc[tid * 9 + 1] = sinf(0.5f * d);
        s_enc[tid * 9 + 2] = sinf(0.25f * d);
        s_enc[tid * 9 + 3] = sinf(0.125f * d);
        s_enc[tid * 9 + 4] = cosf(d);
        s_enc[tid * 9 + 5] = cosf(0.5f * d);
        s_enc[tid * 9 + 6] = cosf(0.25f * d);
        s_enc[tid * 9 + 7] = cosf(0.125f * d);
        s_enc[tid * 9 + 8] = d;
        s_nb[tid] = g_nbidx[(size_t)bi * KK + tid];
    }
    if (tid < 3) { s_geo[tid] = coors[(size_t)bi * 3 + tid]; s_geo[3 + tid] = g_cm[(size_t)bi * 3 + tid]; }
    __syncthreads();

    int lane = tid & 31, wid = tid >> 5;
    float cb2r = cb2g[0], xb2r = xb2g[0];
    float ci0 = s_geo[0], ci1 = s_geo[1], ci2 = s_geo[2];
    float ai0 = s_geo[3], ai1 = s_geo[4], ai2 = s_geo[5];
    const float* cb3 = coors + (size_t)b * NN * 3;
    const float* cmb = g_cm  + (size_t)b * NN * 3;
    float caccl = 0.f;

    #pragma unroll 1
    for (int q = 0; q < 4; q++) {
        int e = wid * 4 + q;
        int j = s_nb[e];
        const float* bv = g_Bv + ((size_t)b * NN + j) * H1;
        float e9[9];
        #pragma unroll
        for (int r = 0; r < 9; r++) e9[r] = s_enc[e * 9 + r];

        // h1 = silu(A_i + Bv_j + enc@W1c + b1)  (530 elems, 17 chunks across warp)
        float h[17];
        #pragma unroll
        for (int tt = 0; tt < 17; tt++) {
            int el = tt * 32 + lane;
            float acc = s_base[el];
            if (el < H1) acc += bv[el];
            #pragma unroll
            for (int r = 0; r < 9; r++) acc = fmaf(e9[r], s_w1c[r * H1P + el], acc);
            h[tt] = silu_f(acc);
        }

        // m = silu(h1 @ W2 + b2)  (16 outputs; butterfly -> all lanes hold all m)
        float p[16];
        #pragma unroll
        for (int c = 0; c < 16; c++) {
            const float* w = s_w2t + c * H1P + lane;
            float acc = 0.f;
            #pragma unroll
            for (int tt = 0; tt < 17; tt++) acc = fmaf(h[tt], w[tt * 32], acc);
            p[c] = acc;
        }
        #pragma unroll
        for (int off = 16; off > 0; off >>= 1) {
            #pragma unroll
            for (int c = 0; c < 16; c++) p[c] += __shfl_xor_sync(0xffffffffu, p[c], off);
        }
        float m[16];
        #pragma unroll
        for (int c = 0; c < 16; c++) m[c] = silu_f(p[c] + s_b2[c]);
        if (lane == 0) {
            #pragma unroll
            for (int c = 0; c < 16; c++) atomicAdd(&s_macc[c], m[c]);
        }

        // coor MLPs: 16 -> 64 -> 1 (two of them), warp-parallel over hidden units
        float hA0 = s_cb1[lane], hA1 = s_cb1[lane + 32];
        float hX0 = s_xb1[lane], hX1 = s_xb1[lane + 32];
        #pragma unroll
        for (int c = 0; c < 16; c++) {
            hA0 = fmaf(m[c], s_cw1[c * 64 + lane],      hA0);
            hA1 = fmaf(m[c], s_cw1[c * 64 + lane + 32], hA1);
            hX0 = fmaf(m[c], s_xw1[c * 64 + lane],      hX0);
            hX1 = fmaf(m[c], s_xw1[c * 64 + lane + 32], hX1);
        }
        hA0 = silu_f(hA0); hA1 = silu_f(hA1); hX0 = silu_f(hX0); hX1 = silu_f(hX1);
        float cw = hA0 * s_cw2[lane] + hA1 * s_cw2[lane + 32];
        float xw = hX0 * s_xw2[lane] + hX1 * s_xw2[lane + 32];
        #pragma unroll
        for (int off = 16; off > 0; off >>= 1) {
            cw += __shfl_xor_sync(0xffffffffu, cw, off);
            xw += __shfl_xor_sync(0xffffffffu, xw, off);
        }
        cw += cb2r; xw += xb2r;

        // geometry: rel = c_i - c_j; cross = cm_i x cm_j; lanes 0..2 accumulate comps
        float cj0 = cb3[3 * j], cj1 = cb3[3 * j + 1], cj2 = cb3[3 * j + 2];
        float bj0 = cmb[3 * j], bj1 = cmb[3 * j + 1], bj2 = cmb[3 * j + 2];
        float rr, xx;
        if (lane == 0)      { rr = ci0 - cj0; xx = ai1 * bj2 - ai2 * bj1; }
        else if (lane == 1) { rr = ci1 - cj1; xx = ai2 * bj0 - ai0 * bj2; }
        else                { rr = ci2 - cj2; xx = ai0 * bj1 - ai1 * bj0; }
        if (lane < 3) caccl = fmaf(cw, rr, fmaf(xw, xx, caccl));
    }
    if (lane < 3) atomicAdd(&s_cacc[lane], caccl);
    __syncthreads();

    // node MLP: hidden = silu(NH + m_i @ node_w1[128:144] + b1)
    {
        float hv = g_NH[(size_t)bi * 256 + tid] + nb1[tid];
        #pragma unroll
        for (int c = 0; c < 16; c++) hv = fmaf(s_macc[c], nw1[(128 + c) * 256 + tid], hv);
        s_hid[tid] = silu_f(hv);
    }
    __syncthreads();
    // out = hidden @ node_w2 + b2 + feats (split-K across thread halves)
    {
        int half = tid >> 7, dcol = tid & 127;
        const float* w2 = nw2 + half * 128 * 128 + dcol;
        const float* hh = s_hid + half * 128;
        float acc = 0.f;
        #pragma unroll 8
        for (int qq = 0; qq < 128; qq++) acc = fmaf(hh[qq], w2[qq * 128], acc);
        if (half == 0) s_out0[dcol] = acc; else s_out1[dcol] = acc;
    }
    __syncthreads();
    if (tid < 128) {
        out[(size_t)bi * 128 + tid] =
            s_out0[tid] + s_out1[tid] + nb2[tid] + feats[(size_t)bi * 128 + tid];
    }
    if (tid < 3) {
        float* outc = out + (size_t)NBI * DD;
        outc[(size_t)bi * 3 + tid] = coors[(size_t)bi * 3 + tid] + s_cacc[tid];
    }
}

#define SMEM_BYTES (17324 * 4)

extern "C" void kernel_launch(void* const* d_in, const int* in_sizes, int n_in,
                              void* d_out, int out_size) {
    const float* feats = (const float*)d_in[0];
    const float* coors = (const float*)d_in[1];
    const float* ew1   = (const float*)d_in[2];
    const float* eb1   = (const float*)d_in[3];
    const float* ew2   = (const float*)d_in[4];
    const float* eb2   = (const float*)d_in[5];
    const float* cw1   = (const float*)d_in[6];
    const float* cb1   = (const float*)d_in[7];
    const float* cw2   = (const float*)d_in[8];
    const float* cb2   = (const float*)d_in[9];
    const float* xw1   = (const float*)d_in[10];
    const float* xb1   = (const float*)d_in[11];
    const float* xw2   = (const float*)d_in[12];
    const float* xb2   = (const float*)d_in[13];
    const float* nw1   = (const float*)d_in[14];
    const float* nb1   = (const float*)d_in[15];
    const float* nw2   = (const float*)d_in[16];
    const float* nb2   = (const float*)d_in[17];
    float* out = (float*)d_out;

    cudaFuncSetAttribute(k_main, cudaFuncAttributeMaxDynamicSharedMemorySize, SMEM_BYTES);

    k_mean<<<NB, 256>>>(coors);
    k_precompAB<<<NBI / 32, 256>>>(feats, ew1);
    k_precompNH<<<NBI / 32, 256>>>(feats, nw1);
    k_topk<<<NBI, 256>>>(coors);
    k_main<<<NBI, 256, SMEM_BYTES>>>(feats, coors, ew1, eb1, ew2, eb2,
                                     cw1, cb1, cw2, cb2, xw1, xb1, xw2, xb2,
                                     nw1, nb1, nw2, nb2, out);
}